// round 15
// baseline (speedup 1.0000x reference)
#include <cuda_runtime.h>
#include <cuda_bf16.h>
#include <math.h>
#include <stdint.h>

// Problem constants (fixed shapes)
constexpr int Bc = 64;    // batch
constexpr int Sc = 512;   // seq
constexpr int Hc = 768;   // hidden
constexpr int Nc = 128;   // nodes
constexpr int Ec = 1024;  // edges per batch
constexpr int GHc = 128;  // gcn hidden
constexpr int FHc = 256;  // fc hidden
constexpr int BNc = Bc * Nc;   // 8192
constexpr int BSc = Bc * Sc;   // 32768

// Scratch (device globals — no allocation allowed)
__device__ int   g_ntok[BNc];
__device__ int   g_indeg[BNc];
__device__ float g_dinv[BNc];
__device__ int   g_tok_off[BNc];
__device__ int   g_edge_off[BNc];
__device__ int   g_toklist[BSc];
__device__ int   g_elist[Bc * Ec];
__device__ __align__(16) float g_nodef[(size_t)BNc * Hc];   // 24 MiB
__device__ __align__(16) float g_a2[(size_t)BNc * GHc];     // 4 MiB (layer2 in)
__device__ __align__(16) float g_h[(size_t)BNc * GHc];      // 4 MiB
__device__ __align__(16) float g_acc[(size_t)BNc * GHc];    // 4 MiB

// ---------------------------------------------------------------------------
// packed f32x2 helpers (Blackwell dual-lane fp32; round-to-nearest per lane,
// bit-identical to scalar FFMA -> exact fp32 semantics)
// ---------------------------------------------------------------------------
__device__ __forceinline__ unsigned long long dup_f32x2(float v) {
    unsigned long long r;
    asm("mov.b64 %0, {%1, %1};" : "=l"(r) : "f"(v));
    return r;
}
#define FMA_F32X2(d, a, b) \
    asm("fma.rn.f32x2 %0, %1, %2, %0;" : "+l"(d) : "l"(a), "l"(b))

// ---------------------------------------------------------------------------
// 1) prep: per-batch CSR build. Block = batch (64 x 256).
// ---------------------------------------------------------------------------
__global__ __launch_bounds__(256)
void prep_v14(const int* __restrict__ submap, const int* __restrict__ eidx) {
    __shared__ int scnt[Nc], sdeg[Nc];
    __shared__ int sscan[256];
    __shared__ int btok[Nc], bedg[Nc];
    __shared__ int sft[Nc], sfe[Nc];
    int b = blockIdx.x, tid = threadIdx.x;

    if (tid < Nc) { scnt[tid] = 0; sdeg[tid] = 0; sft[tid] = 0; sfe[tid] = 0; }
    __syncthreads();

    for (int i = tid; i < Sc; i += 256) atomicAdd(&scnt[submap[b * Sc + i]], 1);
    for (int e = tid; e < Ec; e += 256) atomicAdd(&sdeg[eidx[b * 2 * Ec + Ec + e]], 1);
    __syncthreads();

    int j = tid & 127;
    sscan[tid] = (tid < 128) ? scnt[j] : sdeg[j];
    __syncthreads();
    for (int off = 1; off < 128; off <<= 1) {
        int x = (j >= off) ? sscan[tid - off] : 0;
        __syncthreads();
        sscan[tid] += x;
        __syncthreads();
    }

    if (tid < Nc) {
        int n = tid;
        int ntok = scnt[n];
        int toff = b * Sc + sscan[n] - ntok;
        int ind  = sdeg[n];
        int eoff = b * Ec + sscan[128 + n] - ind;
        g_ntok[b * Nc + n] = ntok;
        g_tok_off[b * Nc + n] = toff;
        g_indeg[b * Nc + n] = ind;
        g_edge_off[b * Nc + n] = eoff;
        g_dinv[b * Nc + n] = rsqrtf(1.f + (float)ind);
        btok[n] = toff; bedg[n] = eoff;
    }
    __syncthreads();

    for (int i = tid; i < Sc; i += 256) {
        int n = submap[b * Sc + i];
        int pos = atomicAdd(&sft[n], 1);
        g_toklist[btok[n] + pos] = b * Sc + i;
    }
    for (int e = tid; e < Ec; e += 256) {
        int src = eidx[b * 2 * Ec + e];
        int dst = eidx[b * 2 * Ec + Ec + e];
        int pos = atomicAdd(&sfe[dst], 1);
        g_elist[bedg[dst] + pos] = b * Nc + src;
    }
}

// ---------------------------------------------------------------------------
// 2) node features (fused gate + segment mean), gather form, two-phase.
//    (R7-proven; fp32 output)
// ---------------------------------------------------------------------------
__global__ __launch_bounds__(256)
void node_feat_v14(const float* __restrict__ lh,
                   const float* __restrict__ wr,
                   const float* __restrict__ brp) {
    __shared__ int   toks[Sc];
    __shared__ float sgate[Sc];
    int node = blockIdx.x;
    int tid = threadIdx.x;
    int lane = tid & 31, wid = tid >> 5;

    int ntok = g_ntok[node];
    int off = g_tok_off[node];
    for (int i = tid; i < ntok; i += 256) toks[i] = g_toklist[off + i];
    __syncthreads();

    float br = brp[0];
    const float4* w4 = (const float4*)wr;
    for (int t = wid; t < ntok; t += 8) {
        const float4* r4 = (const float4*)(lh + (size_t)toks[t] * Hc);
        float p = 0.f;
#pragma unroll
        for (int jj = 0; jj < 6; ++jj) {
            float4 a = r4[lane + jj * 32];
            float4 w = __ldg(&w4[lane + jj * 32]);
            p += a.x * w.x + a.y * w.y + a.z * w.z + a.w * w.w;
        }
#pragma unroll
        for (int o = 16; o; o >>= 1) p += __shfl_xor_sync(0xffffffffu, p, o);
        if (lane == 0) sgate[t] = 1.f / (1.f + expf(-(p + br)));
    }
    __syncthreads();

    float a0 = 0.f, a1 = 0.f, a2 = 0.f;
    for (int t = 0; t < ntok; ++t) {
        const float* row = lh + (size_t)toks[t] * Hc;
        float g = sgate[t];
        a0 += row[tid] * g;
        a1 += row[tid + 256] * g;
        a2 += row[tid + 512] * g;
    }

    float cinv = 1.f / fmaxf((float)ntok, 1.f);
    float* od = g_nodef + (size_t)node * Hc;
    od[tid]       = a0 * cinv;
    od[tid + 256] = a1 * cinv;
    od[tid + 512] = a2 * cinv;
}

// ---------------------------------------------------------------------------
// 3) GEMM (exact fp32, packed f32x2 FMA): g_h[8192x128] = A[8192xK] @ W[Kx128]
//    32x128 block tile, 128 threads, 4 rows x 4 col-pairs per thread,
//    K-tile 32. A staged transposed AND lane-duplicated as u64 (LDS.64
//    broadcast, no packing in inner loop); B pairs loaded as ulonglong2.
//    SRC: 0 -> A = g_nodef; 1 -> A = g_a2.
// ---------------------------------------------------------------------------
template <int K, int SRC>
__global__ __launch_bounds__(128)
void gemm_v14(const float* __restrict__ Bm) {
    const float* __restrict__ A = (SRC == 0) ? g_nodef : g_a2;
    float* __restrict__ C = g_h;
    __shared__ unsigned long long As2[32][33];   // [k][row] = {a,a} (8.4 KB)
    __shared__ float Bs[32][128];                // 16 KB
    int tid = threadIdx.x;
    int tx = tid & 15, ty = tid >> 4;
    int rowBase = blockIdx.x * 32;

    unsigned long long acc[4][4];
#pragma unroll
    for (int i = 0; i < 4; ++i)
#pragma unroll
        for (int j = 0; j < 4; ++j) acc[i][j] = 0ULL;

    for (int k0 = 0; k0 < K; k0 += 32) {
#pragma unroll
        for (int t = 0; t < 2; ++t) {                      // A: 32x32 = 256 f4
            int idx = tid + t * 128;
            int r = idx >> 3, q = idx & 7;
            float4 av = *(const float4*)&A[(size_t)(rowBase + r) * K + k0 + (q << 2)];
            As2[(q << 2) + 0][r] = dup_f32x2(av.x);
            As2[(q << 2) + 1][r] = dup_f32x2(av.y);
            As2[(q << 2) + 2][r] = dup_f32x2(av.z);
            As2[(q << 2) + 3][r] = dup_f32x2(av.w);
        }
#pragma unroll
        for (int t = 0; t < 8; ++t) {                      // B: 32x128 = 1024 f
            int idx = tid + t * 128;
            int kb = idx >> 5, c4 = idx & 31;
            *(float4*)&Bs[kb][c4 << 2] =
                *(const float4*)&Bm[(size_t)(k0 + kb) * 128 + (c4 << 2)];
        }
        __syncthreads();
#pragma unroll
        for (int kk = 0; kk < 32; ++kk) {
            unsigned long long ad[4];
#pragma unroll
            for (int i = 0; i < 4; ++i) ad[i] = As2[kk][(ty << 2) + i];
            ulonglong2 b01 = *(const ulonglong2*)&Bs[kk][tx << 3];
            ulonglong2 b23 = *(const ulonglong2*)&Bs[kk][(tx << 3) + 4];
            unsigned long long bp[4] = {b01.x, b01.y, b23.x, b23.y};
#pragma unroll
            for (int i = 0; i < 4; ++i)
#pragma unroll
                for (int j = 0; j < 4; ++j) FMA_F32X2(acc[i][j], ad[i], bp[j]);
        }
        __syncthreads();
    }
#pragma unroll
    for (int i = 0; i < 4; ++i) {
        size_t row = rowBase + (ty << 2) + i;
        ulonglong2 v0; v0.x = acc[i][0]; v0.y = acc[i][1];
        ulonglong2 v1; v1.x = acc[i][2]; v1.y = acc[i][3];
        *(ulonglong2*)&C[row * 128 + (tx << 3)] = v0;
        *(ulonglong2*)&C[row * 128 + (tx << 3) + 4] = v1;
    }
}

// ---------------------------------------------------------------------------
// 4) message passing, gather form (R7-proven). RELU=1: emit relu(acc + b1)
//    -> g_a2 (layer-2 input). RELU=0: emit raw fp32 -> g_acc (for pooling).
// ---------------------------------------------------------------------------
template <int RELU>
__global__ __launch_bounds__(128)
void msg_gather_v14(const float* __restrict__ bias) {
    __shared__ int ssrc[128];
    int node = blockIdx.x;
    int tid = threadIdx.x;
    int nd = g_indeg[node];
    int off = g_edge_off[node];
    float di = g_dinv[node];
    float acc = g_h[(size_t)node * GHc + tid] * di * di;

    for (int c0 = 0; c0 < nd; c0 += 128) {
        int m = min(128, nd - c0);
        __syncthreads();
        if (tid < m) ssrc[tid] = g_elist[off + c0 + tid];
        __syncthreads();
        int j = 0;
        for (; j + 4 <= m; j += 4) {
            int s0 = ssrc[j], s1 = ssrc[j+1], s2 = ssrc[j+2], s3 = ssrc[j+3];
            float h0 = g_h[(size_t)s0 * GHc + tid];
            float h1 = g_h[(size_t)s1 * GHc + tid];
            float h2 = g_h[(size_t)s2 * GHc + tid];
            float h3 = g_h[(size_t)s3 * GHc + tid];
            acc += h0 * (g_dinv[s0] * di) + h1 * (g_dinv[s1] * di)
                 + h2 * (g_dinv[s2] * di) + h3 * (g_dinv[s3] * di);
        }
        for (; j < m; ++j) {
            int s0 = ssrc[j];
            acc += g_h[(size_t)s0 * GHc + tid] * (g_dinv[s0] * di);
        }
    }
    if (RELU) {
        g_a2[(size_t)node * GHc + tid] = fmaxf(acc + bias[tid], 0.f);
    } else {
        g_acc[(size_t)node * GHc + tid] = acc;
    }
}

// ---------------------------------------------------------------------------
// 5) head (pool fused): pooled = mean_n relu(acc + b2); then 2-layer MLP
// ---------------------------------------------------------------------------
__global__ __launch_bounds__(256)
void fc_v14(const float* __restrict__ lh,
            const float* __restrict__ b2,
            const float* __restrict__ Wf1,
            const float* __restrict__ bf1,
            const float* __restrict__ Wf2,
            const float* __restrict__ bf2,
            float* __restrict__ out) {
    __shared__ float sin_[Hc + GHc];
    __shared__ float psum[GHc];
    __shared__ float red[4][FHc];
    __shared__ float rr[2][8];
    int b = blockIdx.x, tid = threadIdx.x;

    for (int i = tid; i < Hc; i += 256)
        sin_[i] = lh[(size_t)b * Sc * Hc + i];
    {
        int d = tid & 127, half = tid >> 7;
        float bias = b2[d];
        float s = 0.f;
        const float* base = g_acc + ((size_t)(b * Nc + half * 64)) * GHc + d;
#pragma unroll 4
        for (int n = 0; n < 64; ++n)
            s += fmaxf(base[(size_t)n * GHc] + bias, 0.f);
        if (half == 1) psum[d] = s;
        __syncthreads();
        if (half == 0) sin_[Hc + d] = (s + psum[d]) * (1.f / Nc);
    }
    __syncthreads();

    int jg = (tid & 63) << 2, ks = tid >> 6;
    float a0 = 0.f, a1 = 0.f, a2 = 0.f, a3 = 0.f;
    for (int k = ks; k < Hc + GHc; k += 4) {
        float s = sin_[k];
        float4 w = *(const float4*)&Wf1[(size_t)k * FHc + jg];
        a0 += s * w.x; a1 += s * w.y; a2 += s * w.z; a3 += s * w.w;
    }
    red[ks][jg + 0] = a0; red[ks][jg + 1] = a1;
    red[ks][jg + 2] = a2; red[ks][jg + 3] = a3;
    __syncthreads();

    int j = tid;
    float h = bf1[j] + red[0][j] + red[1][j] + red[2][j] + red[3][j];
    h = fmaxf(h, 0.f);
    float p0 = h * Wf2[2 * j], p1 = h * Wf2[2 * j + 1];
#pragma unroll
    for (int o = 16; o; o >>= 1) {
        p0 += __shfl_xor_sync(0xffffffffu, p0, o);
        p1 += __shfl_xor_sync(0xffffffffu, p1, o);
    }
    if ((tid & 31) == 0) { rr[0][tid >> 5] = p0; rr[1][tid >> 5] = p1; }
    __syncthreads();
    if (tid == 0) {
        float t0 = 0.f, t1 = 0.f;
        for (int w = 0; w < 8; ++w) { t0 += rr[0][w]; t1 += rr[1][w]; }
        out[b * 2 + 0] = t0 + bf2[0];
        out[b * 2 + 1] = t1 + bf2[1];
    }
}

// ---------------------------------------------------------------------------
extern "C" void kernel_launch(void* const* d_in, const int* in_sizes, int n_in,
                              void* d_out, int out_size) {
    const float* lh     = (const float*)d_in[0];
    const int*   submap = (const int*)d_in[1];
    const int*   eidx   = (const int*)d_in[2];
    // d_in[3] = num_nodes (constant 128)
    const float* wr  = (const float*)d_in[4];
    const float* br  = (const float*)d_in[5];
    const float* W1  = (const float*)d_in[6];
    const float* b1  = (const float*)d_in[7];
    const float* W2  = (const float*)d_in[8];
    const float* b2  = (const float*)d_in[9];
    const float* Wf1 = (const float*)d_in[10];
    const float* bf1 = (const float*)d_in[11];
    const float* Wf2 = (const float*)d_in[12];
    const float* bf2 = (const float*)d_in[13];
    float* out = (float*)d_out;

    (void)in_sizes; (void)n_in; (void)out_size;

    prep_v14<<<Bc, 256>>>(submap, eidx);
    node_feat_v14<<<BNc, 256>>>(lh, wr, br);

    // layer 1: g_h = nodef @ W1 ; propagate -> g_a2 = relu(. + b1)
    gemm_v14<Hc, 0><<<BNc / 32, 128>>>(W1);
    msg_gather_v14<1><<<BNc, 128>>>(b1);

    // layer 2: g_h = g_a2 @ W2 ; propagate -> g_acc
    gemm_v14<GHc, 1><<<BNc / 32, 128>>>(W2);
    msg_gather_v14<0><<<BNc, 128>>>(b1);

    fc_v14<<<Bc, 256>>>(lh, b2, Wf1, bf1, Wf2, bf2, out);
}

// round 17
// speedup vs baseline: 1.0459x; 1.0459x over previous
#include <cuda_runtime.h>
#include <cuda_bf16.h>
#include <math.h>
#include <stdint.h>

// Problem constants (fixed shapes)
constexpr int Bc = 64;    // batch
constexpr int Sc = 512;   // seq
constexpr int Hc = 768;   // hidden
constexpr int Nc = 128;   // nodes
constexpr int Ec = 1024;  // edges per batch
constexpr int GHc = 128;  // gcn hidden
constexpr int FHc = 256;  // fc hidden
constexpr int BNc = Bc * Nc;   // 8192
constexpr int BSc = Bc * Sc;   // 32768

// Scratch (device globals — no allocation allowed)
__device__ int   g_ntok[BNc];
__device__ int   g_indeg[BNc];
__device__ float g_dinv[BNc];
__device__ int   g_tok_off[BNc];
__device__ int   g_edge_off[BNc];
__device__ int   g_toklist[BSc];
__device__ int   g_elist[Bc * Ec];
__device__ __align__(16) float g_nodef[(size_t)BNc * Hc];   // 24 MiB
__device__ __align__(16) float g_a2[(size_t)BNc * GHc];     // 4 MiB (layer2 in)
__device__ __align__(16) float g_h[(size_t)BNc * GHc];      // 4 MiB
__device__ __align__(16) float g_acc[(size_t)BNc * GHc];    // 4 MiB

// ---------------------------------------------------------------------------
// 1a) prep_csr: per-batch histograms + scan -> offsets/degrees. Block = batch.
// ---------------------------------------------------------------------------
__global__ __launch_bounds__(256)
void prep_csr_v17(const int* __restrict__ submap, const int* __restrict__ eidx) {
    __shared__ int scnt[Nc], sdeg[Nc];
    __shared__ int sscan[256];
    int b = blockIdx.x, tid = threadIdx.x;

    if (tid < Nc) { scnt[tid] = 0; sdeg[tid] = 0; }
    __syncthreads();

    for (int i = tid; i < Sc; i += 256) atomicAdd(&scnt[submap[b * Sc + i]], 1);
    for (int e = tid; e < Ec; e += 256) atomicAdd(&sdeg[eidx[b * 2 * Ec + Ec + e]], 1);
    __syncthreads();

    int j = tid & 127;
    sscan[tid] = (tid < 128) ? scnt[j] : sdeg[j];
    __syncthreads();
    for (int off = 1; off < 128; off <<= 1) {
        int x = (j >= off) ? sscan[tid - off] : 0;
        __syncthreads();
        sscan[tid] += x;
        __syncthreads();
    }

    if (tid < Nc) {
        int n = tid;
        int ntok = scnt[n];
        int ind  = sdeg[n];
        g_ntok[b * Nc + n] = ntok;
        g_tok_off[b * Nc + n] = b * Sc + sscan[n] - ntok;
        g_indeg[b * Nc + n] = ind;
        g_edge_off[b * Nc + n] = b * Ec + sscan[128 + n] - ind;
        g_dinv[b * Nc + n] = rsqrtf(1.f + (float)ind);
    }
}

// ---------------------------------------------------------------------------
// 1b) prep_fill: CSR fills with smem cursors. Block = batch.
// ---------------------------------------------------------------------------
__global__ __launch_bounds__(256)
void prep_fill_v17(const int* __restrict__ submap, const int* __restrict__ eidx) {
    __shared__ int btok[Nc], bedg[Nc];
    __shared__ int sft[Nc], sfe[Nc];
    int b = blockIdx.x, tid = threadIdx.x;

    if (tid < Nc) {
        btok[tid] = g_tok_off[b * Nc + tid];
        bedg[tid] = g_edge_off[b * Nc + tid];
        sft[tid] = 0; sfe[tid] = 0;
    }
    __syncthreads();

    for (int i = tid; i < Sc; i += 256) {
        int n = submap[b * Sc + i];
        int pos = atomicAdd(&sft[n], 1);
        g_toklist[btok[n] + pos] = b * Sc + i;
    }
    for (int e = tid; e < Ec; e += 256) {
        int src = eidx[b * 2 * Ec + e];
        int dst = eidx[b * 2 * Ec + Ec + e];
        int pos = atomicAdd(&sfe[dst], 1);
        g_elist[bedg[dst] + pos] = b * Nc + src;
    }
}

// ---------------------------------------------------------------------------
// 2) node features (fused gate + segment mean), gather form, two-phase.
//    Phase A: warp-per-token gate dot. Phase B: float4 accumulation
//    (192 active threads x 1 float4 = 768 cols; 4x fewer load instrs).
// ---------------------------------------------------------------------------
__global__ __launch_bounds__(256)
void node_feat_v17(const float* __restrict__ lh,
                   const float* __restrict__ wr,
                   const float* __restrict__ brp) {
    __shared__ int   toks[Sc];
    __shared__ float sgate[Sc];
    int node = blockIdx.x;
    int tid = threadIdx.x;
    int lane = tid & 31, wid = tid >> 5;

    int ntok = g_ntok[node];
    int off = g_tok_off[node];
    for (int i = tid; i < ntok; i += 256) toks[i] = g_toklist[off + i];
    __syncthreads();

    float br = brp[0];
    const float4* w4 = (const float4*)wr;
    for (int t = wid; t < ntok; t += 8) {
        const float4* r4 = (const float4*)(lh + (size_t)toks[t] * Hc);
        float p = 0.f;
#pragma unroll
        for (int jj = 0; jj < 6; ++jj) {
            float4 a = r4[lane + jj * 32];
            float4 w = __ldg(&w4[lane + jj * 32]);
            p += a.x * w.x + a.y * w.y + a.z * w.z + a.w * w.w;
        }
#pragma unroll
        for (int o = 16; o; o >>= 1) p += __shfl_xor_sync(0xffffffffu, p, o);
        if (lane == 0) sgate[t] = 1.f / (1.f + expf(-(p + br)));
    }
    __syncthreads();

    if (tid < 192) {                      // 192 * 4 = 768 cols
        float a0 = 0.f, a1 = 0.f, a2 = 0.f, a3 = 0.f;
        for (int t = 0; t < ntok; ++t) {
            const float4* row4 = (const float4*)(lh + (size_t)toks[t] * Hc);
            float4 v = row4[tid];
            float g = sgate[t];
            a0 += v.x * g; a1 += v.y * g; a2 += v.z * g; a3 += v.w * g;
        }
        float cinv = 1.f / fmaxf((float)ntok, 1.f);
        float4 o = make_float4(a0 * cinv, a1 * cinv, a2 * cinv, a3 * cinv);
        ((float4*)(g_nodef + (size_t)node * Hc))[tid] = o;
    }
}

// ---------------------------------------------------------------------------
// 3) GEMM (R7-proven scalar): g_h[8192 x 128] = A[8192 x K] @ W[K x 128]
//    32x128 block tile, 128 threads, 4x8 thread tile, K-tile 32, 256 CTAs.
//    SRC: 0 -> A = g_nodef; 1 -> A = g_a2.
// ---------------------------------------------------------------------------
template <int K, int SRC>
__global__ __launch_bounds__(128)
void gemm_v17(const float* __restrict__ Bm) {
    const float* __restrict__ A = (SRC == 0) ? g_nodef : g_a2;
    float* __restrict__ C = g_h;
    __shared__ float As[32][33];   // transposed; pad 33 -> conflict-free
    __shared__ float Bs[32][128];
    int tid = threadIdx.x;
    int tx = tid & 15, ty = tid >> 4;
    int rowBase = blockIdx.x * 32;

    float acc[4][8];
#pragma unroll
    for (int i = 0; i < 4; ++i)
#pragma unroll
        for (int j = 0; j < 8; ++j) acc[i][j] = 0.f;

    for (int k0 = 0; k0 < K; k0 += 32) {
#pragma unroll
        for (int t = 0; t < 2; ++t) {                      // A: 32x32 = 256 f4
            int idx = tid + t * 128;
            int r = idx >> 3, q = idx & 7;
            float4 av = *(const float4*)&A[(size_t)(rowBase + r) * K + k0 + (q << 2)];
            As[(q << 2) + 0][r] = av.x;
            As[(q << 2) + 1][r] = av.y;
            As[(q << 2) + 2][r] = av.z;
            As[(q << 2) + 3][r] = av.w;
        }
#pragma unroll
        for (int t = 0; t < 8; ++t) {                      // B: 32x128
            int idx = tid + t * 128;
            int kb = idx >> 5, c4 = idx & 31;
            *(float4*)&Bs[kb][c4 << 2] =
                *(const float4*)&Bm[(size_t)(k0 + kb) * 128 + (c4 << 2)];
        }
        __syncthreads();
#pragma unroll
        for (int kk = 0; kk < 32; ++kk) {
            float av[4];
#pragma unroll
            for (int i = 0; i < 4; ++i) av[i] = As[kk][(ty << 2) + i];
            float4 b0 = *(const float4*)&Bs[kk][tx << 3];
            float4 b1 = *(const float4*)&Bs[kk][(tx << 3) + 4];
            float bv[8] = {b0.x, b0.y, b0.z, b0.w, b1.x, b1.y, b1.z, b1.w};
#pragma unroll
            for (int i = 0; i < 4; ++i)
#pragma unroll
                for (int j = 0; j < 8; ++j) acc[i][j] += av[i] * bv[j];
        }
        __syncthreads();
    }
#pragma unroll
    for (int i = 0; i < 4; ++i) {
        size_t row = rowBase + (ty << 2) + i;
        float4 v0 = make_float4(acc[i][0], acc[i][1], acc[i][2], acc[i][3]);
        float4 v1 = make_float4(acc[i][4], acc[i][5], acc[i][6], acc[i][7]);
        *(float4*)&C[row * 128 + (tx << 3)] = v0;
        *(float4*)&C[row * 128 + (tx << 3) + 4] = v1;
    }
}

// ---------------------------------------------------------------------------
// 4) message passing, gather form (R7-proven). RELU=1: emit relu(acc + b1)
//    -> g_a2 (layer-2 input). RELU=0: emit raw fp32 -> g_acc (for pooling).
// ---------------------------------------------------------------------------
template <int RELU>
__global__ __launch_bounds__(128)
void msg_gather_v17(const float* __restrict__ bias) {
    __shared__ int ssrc[128];
    int node = blockIdx.x;
    int tid = threadIdx.x;
    int nd = g_indeg[node];
    int off = g_edge_off[node];
    float di = g_dinv[node];
    float acc = g_h[(size_t)node * GHc + tid] * di * di;

    for (int c0 = 0; c0 < nd; c0 += 128) {
        int m = min(128, nd - c0);
        __syncthreads();
        if (tid < m) ssrc[tid] = g_elist[off + c0 + tid];
        __syncthreads();
        int j = 0;
        for (; j + 4 <= m; j += 4) {
            int s0 = ssrc[j], s1 = ssrc[j+1], s2 = ssrc[j+2], s3 = ssrc[j+3];
            float h0 = g_h[(size_t)s0 * GHc + tid];
            float h1 = g_h[(size_t)s1 * GHc + tid];
            float h2 = g_h[(size_t)s2 * GHc + tid];
            float h3 = g_h[(size_t)s3 * GHc + tid];
            acc += h0 * (g_dinv[s0] * di) + h1 * (g_dinv[s1] * di)
                 + h2 * (g_dinv[s2] * di) + h3 * (g_dinv[s3] * di);
        }
        for (; j < m; ++j) {
            int s0 = ssrc[j];
            acc += g_h[(size_t)s0 * GHc + tid] * (g_dinv[s0] * di);
        }
    }
    if (RELU) {
        g_a2[(size_t)node * GHc + tid] = fmaxf(acc + bias[tid], 0.f);
    } else {
        g_acc[(size_t)node * GHc + tid] = acc;
    }
}

// ---------------------------------------------------------------------------
// 5) head (pool fused): pooled = mean_n relu(acc + b2); then 2-layer MLP
// ---------------------------------------------------------------------------
__global__ __launch_bounds__(256)
void fc_v17(const float* __restrict__ lh,
            const float* __restrict__ b2,
            const float* __restrict__ Wf1,
            const float* __restrict__ bf1,
            const float* __restrict__ Wf2,
            const float* __restrict__ bf2,
            float* __restrict__ out) {
    __shared__ float sin_[Hc + GHc];
    __shared__ float psum[GHc];
    __shared__ float red[4][FHc];
    __shared__ float rr[2][8];
    int b = blockIdx.x, tid = threadIdx.x;

    for (int i = tid; i < Hc; i += 256)
        sin_[i] = lh[(size_t)b * Sc * Hc + i];
    {
        int d = tid & 127, half = tid >> 7;
        float bias = b2[d];
        float s = 0.f;
        const float* base = g_acc + ((size_t)(b * Nc + half * 64)) * GHc + d;
#pragma unroll 4
        for (int n = 0; n < 64; ++n)
            s += fmaxf(base[(size_t)n * GHc] + bias, 0.f);
        if (half == 1) psum[d] = s;
        __syncthreads();
        if (half == 0) sin_[Hc + d] = (s + psum[d]) * (1.f / Nc);
    }
    __syncthreads();

    int jg = (tid & 63) << 2, ks = tid >> 6;
    float a0 = 0.f, a1 = 0.f, a2 = 0.f, a3 = 0.f;
    for (int k = ks; k < Hc + GHc; k += 4) {
        float s = sin_[k];
        float4 w = *(const float4*)&Wf1[(size_t)k * FHc + jg];
        a0 += s * w.x; a1 += s * w.y; a2 += s * w.z; a3 += s * w.w;
    }
    red[ks][jg + 0] = a0; red[ks][jg + 1] = a1;
    red[ks][jg + 2] = a2; red[ks][jg + 3] = a3;
    __syncthreads();

    int j = tid;
    float h = bf1[j] + red[0][j] + red[1][j] + red[2][j] + red[3][j];
    h = fmaxf(h, 0.f);
    float p0 = h * Wf2[2 * j], p1 = h * Wf2[2 * j + 1];
#pragma unroll
    for (int o = 16; o; o >>= 1) {
        p0 += __shfl_xor_sync(0xffffffffu, p0, o);
        p1 += __shfl_xor_sync(0xffffffffu, p1, o);
    }
    if ((tid & 31) == 0) { rr[0][tid >> 5] = p0; rr[1][tid >> 5] = p1; }
    __syncthreads();
    if (tid == 0) {
        float t0 = 0.f, t1 = 0.f;
        for (int w = 0; w < 8; ++w) { t0 += rr[0][w]; t1 += rr[1][w]; }
        out[b * 2 + 0] = t0 + bf2[0];
        out[b * 2 + 1] = t1 + bf2[1];
    }
}

// ---------------------------------------------------------------------------
extern "C" void kernel_launch(void* const* d_in, const int* in_sizes, int n_in,
                              void* d_out, int out_size) {
    const float* lh     = (const float*)d_in[0];
    const int*   submap = (const int*)d_in[1];
    const int*   eidx   = (const int*)d_in[2];
    // d_in[3] = num_nodes (constant 128)
    const float* wr  = (const float*)d_in[4];
    const float* br  = (const float*)d_in[5];
    const float* W1  = (const float*)d_in[6];
    const float* b1  = (const float*)d_in[7];
    const float* W2  = (const float*)d_in[8];
    const float* b2  = (const float*)d_in[9];
    const float* Wf1 = (const float*)d_in[10];
    const float* bf1 = (const float*)d_in[11];
    const float* Wf2 = (const float*)d_in[12];
    const float* bf2 = (const float*)d_in[13];
    float* out = (float*)d_out;

    (void)in_sizes; (void)n_in; (void)out_size;

    prep_csr_v17<<<Bc, 256>>>(submap, eidx);     // launch 1
    prep_fill_v17<<<Bc, 256>>>(submap, eidx);    // launch 2
    node_feat_v17<<<BNc, 256>>>(lh, wr, br);     // launch 3

    // layer 1: g_h = nodef @ W1 ; propagate -> g_a2 = relu(. + b1)
    gemm_v17<Hc, 0><<<BNc / 32, 128>>>(W1);      // launch 4 <- ncu profiles this
    msg_gather_v17<1><<<BNc, 128>>>(b1);         // launch 5

    // layer 2: g_h = g_a2 @ W2 ; propagate -> g_acc
    gemm_v17<GHc, 1><<<BNc / 32, 128>>>(W2);     // launch 6
    msg_gather_v17<0><<<BNc, 128>>>(b1);         // launch 7

    fc_v17<<<Bc, 256>>>(lh, b2, Wf1, bf1, Wf2, bf2, out);  // launch 8
}